// round 3
// baseline (speedup 1.0000x reference)
#include <cuda_runtime.h>
#include <stdint.h>

#define BATCH 128
#define NANCH 16800
#define NQ (NANCH / 4)            // 4200 uint4/float4 per row
#define CHUNKS 8
#define CHUNK_Q (NQ / CHUNKS)     // 525
#define NEG_RATIO 3
#define SCALE_XY 10.0f
#define SCALE_WH 5.0f
#define T1 256
#define T2 512
#define NIT2 ((NQ + T2 - 1) / T2) // 9
#define FLT_EPS_ 1.1920929e-07f

// Scratch (allocation-free rule: __device__ globals)
__device__ float    g_row_lossb[BATCH];
__device__ float    g_row_bcepos[BATCH];
__device__ float    g_row_lossl[BATCH];
__device__ int      g_row_posn[BATCH];
__device__ int      g_done = 0;
__device__ unsigned g_bits[(size_t)BATCH * NANCH];  // labels_neg bit patterns

extern __shared__ unsigned s_bits[];

__device__ __forceinline__ float warp_sum(float v) {
    #pragma unroll
    for (int o = 16; o > 0; o >>= 1) v += __shfl_down_sync(0xFFFFFFFFu, v, o);
    return v;
}
__device__ __forceinline__ int warp_sum_i(int v) {
    #pragma unroll
    for (int o = 16; o > 0; o >>= 1) v += __shfl_down_sync(0xFFFFFFFFu, v, o);
    return v;
}

// ---------------- Pass 1: streaming BCE + positive SmoothL1 ----------------
__global__ __launch_bounds__(T1)
void od_pass1(const float* __restrict__ pbboxs,
              const float* __restrict__ plabels,
              const float* __restrict__ gbboxs,
              const float* __restrict__ glabels,
              const float* __restrict__ ancs) {
    const int row  = blockIdx.y;
    const int base = blockIdx.x * CHUNK_Q;
    const int tid  = threadIdx.x;
    const int lane = tid & 31;
    const int wid  = tid >> 5;

    const float4* pl4 = (const float4*)(plabels + (size_t)row * NANCH);
    const float4* gl4 = (const float4*)(glabels + (size_t)row * NANCH);
    const float4* pb  = (const float4*)pbboxs + (size_t)row * NANCH;
    const float4* gb  = (const float4*)gbboxs + (size_t)row * NANCH;
    const float4* an  = (const float4*)ancs;
    uint4* outb = (uint4*)(g_bits + (size_t)row * NANCH);

    float acc_sl1 = 0.f, acc_bce = 0.f;
    int cnt = 0;

    for (int i4 = base + tid; i4 < base + CHUNK_Q; i4 += T1) {
        float4 xv = pl4[i4];
        float4 yv = gl4[i4];
        uint4 w;
        #pragma unroll
        for (int c = 0; c < 4; c++) {
            float x = (c == 0) ? xv.x : (c == 1) ? xv.y : (c == 2) ? xv.z : xv.w;
            float y = (c == 0) ? yv.x : (c == 1) ? yv.y : (c == 2) ? yv.z : yv.w;
            float bce = fmaxf(x, 0.f) - x * y + __logf(1.f + __expf(-fabsf(x)));
            unsigned bits;
            if (y > 0.f) {
                const int i = 4 * i4 + c;
                float4 p = pb[i];
                float4 g = gb[i];
                float4 a = an[i];
                float inv_az = 1.f / a.z;
                float inv_aw = 1.f / a.w;
                float d0 = p.x - SCALE_XY * (g.x - a.x) * inv_az;
                float d1 = p.y - SCALE_XY * (g.y - a.y) * inv_aw;
                float d2 = p.z - SCALE_WH * __logf(g.z * inv_az);
                float d3 = p.w - SCALE_WH * __logf(g.w * inv_aw);
                float sl1 = 0.f, ad;
                ad = fabsf(d0); sl1 += (ad < 1.f) ? 0.5f * d0 * d0 : ad - 0.5f;
                ad = fabsf(d1); sl1 += (ad < 1.f) ? 0.5f * d1 * d1 : ad - 0.5f;
                ad = fabsf(d2); sl1 += (ad < 1.f) ? 0.5f * d2 * d2 : ad - 0.5f;
                ad = fabsf(d3); sl1 += (ad < 1.f) ? 0.5f * d3 * d3 : ad - 0.5f;
                acc_sl1 += sl1;
                acc_bce += bce;
                cnt++;
                bits = 0u;
            } else {
                bits = __float_as_uint(bce);  // bce >= 0: bit order == value order
            }
            if (c == 0) w.x = bits; else if (c == 1) w.y = bits;
            else if (c == 2) w.z = bits; else w.w = bits;
        }
        outb[i4] = w;
    }

    __shared__ float r1[T1 / 32], r2[T1 / 32];
    __shared__ int   r3[T1 / 32];
    float w1 = warp_sum(acc_sl1);
    float w2 = warp_sum(acc_bce);
    int   w3 = warp_sum_i(cnt);
    if (lane == 0) { r1[wid] = w1; r2[wid] = w2; r3[wid] = w3; }
    __syncthreads();
    if (tid == 0) {
        float s1 = 0.f, s2 = 0.f; int s3 = 0;
        #pragma unroll
        for (int i = 0; i < T1 / 32; i++) { s1 += r1[i]; s2 += r2[i]; s3 += r3[i]; }
        if (s1 != 0.f) atomicAdd(&g_row_lossb[row], s1);
        if (s2 != 0.f) atomicAdd(&g_row_bcepos[row], s2);
        if (s3 != 0)   atomicAdd(&g_row_posn[row], s3);
    }
}

// ------------- Pass 2: per-row radix top-K select + final reduce -------------
__global__ __launch_bounds__(T2, 1)
void od_pass2(float* __restrict__ out, int out_size) {
    const int b    = blockIdx.x;
    const int tid  = threadIdx.x;
    const int lane = tid & 31;

    __shared__ unsigned hist[256];
    __shared__ unsigned s_prefix;
    __shared__ int   s_kr;
    __shared__ float s_sumgt;
    __shared__ int   s_last;
    __shared__ float s_red[48];

    const uint4* gb4 = (const uint4*)(g_bits + (size_t)b * NANCH);
    const int pos_num = g_row_posn[b];
    int K = NEG_RATIO * pos_num;
    if (K > NANCH) K = NANCH;

    float sum_top = 0.f;
    if (K > 0) {
        if (tid < 256) hist[tid] = 0u;
        if (tid == 0) s_sumgt = 0.f;
        __syncthreads();

        // Load row bits to smem fused with radix round 0 (top byte)
        for (int it = 0; it < NIT2; it++) {
            const int i4 = tid + it * T2;
            const bool valid = (i4 < NQ);
            uint4 w = make_uint4(0, 0, 0, 0);
            if (valid) {
                w = gb4[i4];
                ((uint4*)s_bits)[i4] = w;
            }
            #pragma unroll
            for (int c = 0; c < 4; c++) {
                unsigned u = (c == 0) ? w.x : (c == 1) ? w.y : (c == 2) ? w.z : w.w;
                unsigned bkt = valid ? (u >> 24) : 0xFFFFFFFFu;
                unsigned m = __match_any_sync(0xFFFFFFFFu, bkt);
                if (valid && lane == (__ffs(m) - 1))
                    atomicAdd(&hist[bkt], (unsigned)__popc(m));
            }
        }
        __syncthreads();

        unsigned prefix = 0;
        int kr = K;
        #pragma unroll
        for (int r = 0; r < 3; r++) {
            // Warp 0: descending suffix-scan over 256 bins, pick bucket
            if (tid < 32) {
                int s[8];
                int run = 0;
                #pragma unroll
                for (int j = 0; j < 8; j++) {
                    run += (int)hist[255 - (tid * 8 + j)];
                    s[j] = run;
                }
                const int tot = run;
                int incl = tot;
                #pragma unroll
                for (int o = 1; o < 32; o <<= 1) {
                    int v = __shfl_up_sync(0xFFFFFFFFu, incl, o);
                    if (lane >= o) incl += v;
                }
                const int excl = incl - tot;
                int found_j = -1;
                #pragma unroll
                for (int j = 0; j < 8; j++)
                    if (found_j < 0 && excl + s[j] >= kr) found_j = j;
                unsigned bal = __ballot_sync(0xFFFFFFFFu, found_j >= 0);
                int winner = __ffs(bal) - 1;
                if (lane == winner) {
                    const int idx = 255 - (tid * 8 + found_j);
                    s_prefix = (prefix << 8) | (unsigned)idx;
                    s_kr = kr - (excl + s[found_j] - (int)hist[idx]);
                }
            }
            __syncthreads();
            prefix = s_prefix;
            kr = s_kr;

            if (r < 2) {
                // Histogram next byte among elements matching prefix
                const int shift = 16 - 8 * r;
                if (tid < 256) hist[tid] = 0u;
                __syncthreads();
                for (int it = 0; it < NIT2; it++) {
                    const int i4 = tid + it * T2;
                    const bool valid = (i4 < NQ);
                    uint4 w = make_uint4(0, 0, 0, 0);
                    if (valid) w = ((const uint4*)s_bits)[i4];
                    #pragma unroll
                    for (int c = 0; c < 4; c++) {
                        unsigned u = (c == 0) ? w.x : (c == 1) ? w.y : (c == 2) ? w.z : w.w;
                        bool ok = valid && ((u >> (shift + 8)) == prefix);
                        unsigned bkt = ok ? ((u >> shift) & 255u) : 0xFFFFFFFFu;
                        unsigned m = __match_any_sync(0xFFFFFFFFu, bkt);
                        if (ok && lane == (__ffs(m) - 1))
                            atomicAdd(&hist[bkt], (unsigned)__popc(m));
                    }
                }
                __syncthreads();
            }
        }

        // Sum of values strictly above the selected 24-bit bin
        float sg = 0.f;
        for (int i4 = tid; i4 < NQ; i4 += T2) {
            uint4 w = ((const uint4*)s_bits)[i4];
            if ((w.x >> 8) > prefix) sg += __uint_as_float(w.x);
            if ((w.y >> 8) > prefix) sg += __uint_as_float(w.y);
            if ((w.z >> 8) > prefix) sg += __uint_as_float(w.z);
            if ((w.w >> 8) > prefix) sg += __uint_as_float(w.w);
        }
        float wg = warp_sum(sg);
        if (lane == 0) atomicAdd(&s_sumgt, wg);
        __syncthreads();
        sum_top = s_sumgt + (float)kr * __uint_as_float((prefix << 8) | 0x80u);
    }

    // Publish row result; last block reduces, writes output, resets scratch
    if (tid == 0) {
        g_row_lossl[b] = g_row_bcepos[b] + sum_top;
        __threadfence();
        int prev = atomicAdd(&g_done, 1);
        s_last = (prev == BATCH - 1);
    }
    __syncthreads();

    if (s_last) {
        float vlb = 0.f, vll = 0.f, vm = 0.f;
        if (tid < BATCH) {
            float pn  = (float)((volatile int*)g_row_posn)[tid];
            float lbv = ((volatile float*)g_row_lossb)[tid];
            float llv = ((volatile float*)g_row_lossl)[tid];
            float mask = (pn > 0.f) ? 1.f : 0.f;
            float wgt  = mask / fmaxf(pn, FLT_EPS_);
            vlb = lbv * wgt;
            vll = llv * wgt;
            vm  = wgt;
            // reset accumulators for next graph replay (values already in regs)
            g_row_posn[tid]   = 0;
            g_row_lossb[tid]  = 0.f;
            g_row_bcepos[tid] = 0.f;
        }
        vlb = warp_sum(vlb);
        vll = warp_sum(vll);
        vm  = warp_sum(vm);
        const int wid = tid >> 5;
        if (lane == 0) {
            s_red[wid * 3 + 0] = vlb;
            s_red[wid * 3 + 1] = vll;
            s_red[wid * 3 + 2] = vm;
        }
        __syncthreads();
        if (tid == 0) {
            float slb = 0.f, sll = 0.f, sm = 0.f;
            #pragma unroll
            for (int w = 0; w < 16; w++) {
                slb += s_red[w * 3 + 0];
                sll += s_red[w * 3 + 1];
                sm  += s_red[w * 3 + 2];
            }
            const float lb = slb / (float)BATCH;
            const float ll = sll / (float)BATCH;
            const float total = (lb + ll) * (sm / (float)BATCH);
            if (out_size >= 1) out[0] = total;
            if (out_size >= 2) out[1] = lb;
            if (out_size >= 3) out[2] = ll;
            g_done = 0;
        }
    }
}

extern "C" void kernel_launch(void* const* d_in, const int* in_sizes, int n_in,
                              void* d_out, int out_size) {
    const float* pbboxs  = (const float*)d_in[0];
    const float* plabels = (const float*)d_in[1];
    const float* gbboxs  = (const float*)d_in[2];
    const float* glabels = (const float*)d_in[3];
    const float* ancs    = (const float*)d_in[4];
    (void)in_sizes; (void)n_in;

    const size_t smem = (size_t)NANCH * sizeof(unsigned);
    cudaFuncSetAttribute(od_pass2,
                         cudaFuncAttributeMaxDynamicSharedMemorySize, (int)smem);

    dim3 grid1(CHUNKS, BATCH);
    od_pass1<<<grid1, T1>>>(pbboxs, plabels, gbboxs, glabels, ancs);
    od_pass2<<<BATCH, T2, smem>>>((float*)d_out, out_size);
}

// round 4
// speedup vs baseline: 1.1024x; 1.1024x over previous
#include <cuda_runtime.h>
#include <stdint.h>

#define BATCH 128
#define NANCH 16800
#define NQ (NANCH / 4)            // 4200 uint4/float4 per row
#define CHUNKS 8
#define CHUNK_Q (NQ / CHUNKS)     // 525
#define NEG_RATIO 3
#define SCALE_XY 10.0f
#define SCALE_WH 5.0f
#define T1 256
#define T2 1024
#define NW2 (T2 / 32)             // 32 warps
#define NIT2 ((NQ + T2 - 1) / T2) // 5
#define FLT_EPS_ 1.1920929e-07f

// Scratch (allocation-free rule: __device__ globals)
__device__ float    g_row_lossb[BATCH];
__device__ float    g_row_bcepos[BATCH];
__device__ float    g_row_lossl[BATCH];
__device__ int      g_row_posn[BATCH];
__device__ int      g_done = 0;
__device__ unsigned g_bits[(size_t)BATCH * NANCH];  // labels_neg bit patterns

extern __shared__ unsigned s_bits[];  // NANCH per row

__device__ __forceinline__ float warp_sum(float v) {
    #pragma unroll
    for (int o = 16; o > 0; o >>= 1) v += __shfl_down_sync(0xFFFFFFFFu, v, o);
    return v;
}
__device__ __forceinline__ int warp_sum_i(int v) {
    #pragma unroll
    for (int o = 16; o > 0; o >>= 1) v += __shfl_down_sync(0xFFFFFFFFu, v, o);
    return v;
}

// ---------------- Pass 1: streaming BCE + positive SmoothL1 ----------------
__global__ __launch_bounds__(T1)
void od_pass1(const float* __restrict__ pbboxs,
              const float* __restrict__ plabels,
              const float* __restrict__ gbboxs,
              const float* __restrict__ glabels,
              const float* __restrict__ ancs) {
    const int row  = blockIdx.y;
    const int base = blockIdx.x * CHUNK_Q;
    const int tid  = threadIdx.x;
    const int lane = tid & 31;
    const int wid  = tid >> 5;

    const float4* pl4 = (const float4*)(plabels + (size_t)row * NANCH);
    const float4* gl4 = (const float4*)(glabels + (size_t)row * NANCH);
    const float4* pb  = (const float4*)pbboxs + (size_t)row * NANCH;
    const float4* gb  = (const float4*)gbboxs + (size_t)row * NANCH;
    const float4* an  = (const float4*)ancs;
    uint4* outb = (uint4*)(g_bits + (size_t)row * NANCH);

    float acc_sl1 = 0.f, acc_bce = 0.f;
    int cnt = 0;

    for (int i4 = base + tid; i4 < base + CHUNK_Q; i4 += T1) {
        float4 xv = pl4[i4];
        float4 yv = gl4[i4];
        uint4 w;
        #pragma unroll
        for (int c = 0; c < 4; c++) {
            float x = (c == 0) ? xv.x : (c == 1) ? xv.y : (c == 2) ? xv.z : xv.w;
            float y = (c == 0) ? yv.x : (c == 1) ? yv.y : (c == 2) ? yv.z : yv.w;
            float bce = fmaxf(x, 0.f) - x * y + __logf(1.f + __expf(-fabsf(x)));
            unsigned bits;
            if (y > 0.f) {
                const int i = 4 * i4 + c;
                float4 p = pb[i];
                float4 g = gb[i];
                float4 a = an[i];
                float inv_az = 1.f / a.z;
                float inv_aw = 1.f / a.w;
                float d0 = p.x - SCALE_XY * (g.x - a.x) * inv_az;
                float d1 = p.y - SCALE_XY * (g.y - a.y) * inv_aw;
                float d2 = p.z - SCALE_WH * __logf(g.z * inv_az);
                float d3 = p.w - SCALE_WH * __logf(g.w * inv_aw);
                float sl1 = 0.f, ad;
                ad = fabsf(d0); sl1 += (ad < 1.f) ? 0.5f * d0 * d0 : ad - 0.5f;
                ad = fabsf(d1); sl1 += (ad < 1.f) ? 0.5f * d1 * d1 : ad - 0.5f;
                ad = fabsf(d2); sl1 += (ad < 1.f) ? 0.5f * d2 * d2 : ad - 0.5f;
                ad = fabsf(d3); sl1 += (ad < 1.f) ? 0.5f * d3 * d3 : ad - 0.5f;
                acc_sl1 += sl1;
                acc_bce += bce;
                cnt++;
                bits = 0u;
            } else {
                bits = __float_as_uint(bce);  // bce >= 0: bit order == value order
            }
            if (c == 0) w.x = bits; else if (c == 1) w.y = bits;
            else if (c == 2) w.z = bits; else w.w = bits;
        }
        outb[i4] = w;
    }

    __shared__ float r1[T1 / 32], r2[T1 / 32];
    __shared__ int   r3[T1 / 32];
    float w1 = warp_sum(acc_sl1);
    float w2 = warp_sum(acc_bce);
    int   w3 = warp_sum_i(cnt);
    if (lane == 0) { r1[wid] = w1; r2[wid] = w2; r3[wid] = w3; }
    __syncthreads();
    if (tid == 0) {
        float s1 = 0.f, s2 = 0.f; int s3 = 0;
        #pragma unroll
        for (int i = 0; i < T1 / 32; i++) { s1 += r1[i]; s2 += r2[i]; s3 += r3[i]; }
        if (s1 != 0.f) atomicAdd(&g_row_lossb[row], s1);
        if (s2 != 0.f) atomicAdd(&g_row_bcepos[row], s2);
        if (s3 != 0)   atomicAdd(&g_row_posn[row], s3);
    }
}

// ---- warp-0 descending suffix-scan bucket select over 256 bins ----
__device__ __forceinline__ void select_bin(const int* __restrict__ hist,
                                           int kr_in, unsigned prefix_in,
                                           unsigned* s_prefix, int* s_kr, int lane) {
    int s[8];
    int run = 0;
    #pragma unroll
    for (int j = 0; j < 8; j++) {
        run += hist[255 - (lane * 8 + j)];
        s[j] = run;
    }
    const int tot = run;
    int incl = tot;
    #pragma unroll
    for (int o = 1; o < 32; o <<= 1) {
        int v = __shfl_up_sync(0xFFFFFFFFu, incl, o);
        if (lane >= o) incl += v;
    }
    const int excl = incl - tot;
    int fj = -1;
    #pragma unroll
    for (int j = 0; j < 8; j++)
        if (fj < 0 && excl + s[j] >= kr_in) fj = j;
    unsigned bal = __ballot_sync(0xFFFFFFFFu, fj >= 0);
    int winner = __ffs(bal) - 1;
    if (lane == winner) {
        const int idx = 255 - (lane * 8 + fj);
        *s_prefix = (prefix_in << 8) | (unsigned)idx;
        *s_kr = kr_in - (excl + s[fj] - hist[idx]);
    }
}

// ------------- Pass 2: per-row radix top-K select + final reduce -------------
__global__ __launch_bounds__(T2, 1)
void od_pass2(float* __restrict__ out, int out_size) {
    const int b    = blockIdx.x;
    const int tid  = threadIdx.x;
    const int lane = tid & 31;
    const int wid  = tid >> 5;

    __shared__ int      s_wh[NW2 * 256];   // per-warp privatized histograms
    __shared__ int      s_hist[256];       // combined
    __shared__ int      s_c2[256];         // sweep-C sub-bin counts
    __shared__ float    s_fsum[256];       // sweep-C sub-bin value sums
    __shared__ unsigned s_prefix;
    __shared__ int      s_kr;
    __shared__ float    s_sumgt, s_sumabove;
    __shared__ int      s_last;
    __shared__ float    s_red[NW2 * 3];

    const uint4* gb4 = (const uint4*)(g_bits + (size_t)b * NANCH);
    const int pos_num = g_row_posn[b];
    int K = NEG_RATIO * pos_num;
    if (K > NANCH) K = NANCH;

    float sum_top = 0.f;
    if (K > 0) {
        // zero per-warp hists (each warp its own) + scalars
        #pragma unroll
        for (int j = lane; j < 256; j += 32) s_wh[wid * 256 + j] = 0;
        if (tid == 0) { s_sumgt = 0.f; s_sumabove = 0.f; }
        if (tid < 256) { s_c2[tid] = 0; s_fsum[tid] = 0.f; }
        __syncthreads();

        // ---- Sweep A: global -> smem copy + top-byte per-warp histogram ----
        #pragma unroll
        for (int it = 0; it < NIT2; it++) {
            const int i4 = tid + it * T2;
            const bool valid = (i4 < NQ);
            uint4 w = make_uint4(0, 0, 0, 0);
            if (valid) {
                w = gb4[i4];
                ((uint4*)s_bits)[i4] = w;
            }
            #pragma unroll
            for (int c = 0; c < 4; c++) {
                unsigned u = (c == 0) ? w.x : (c == 1) ? w.y : (c == 2) ? w.z : w.w;
                unsigned bkt = valid ? (u >> 24) : 0x100u;
                unsigned m = __match_any_sync(0xFFFFFFFFu, bkt);
                if (valid && lane == (__ffs(m) - 1))
                    s_wh[wid * 256 + bkt] += __popc(m);
            }
        }
        __syncthreads();
        if (tid < 256) {
            int t = 0;
            #pragma unroll
            for (int w = 0; w < NW2; w++) t += s_wh[w * 256 + tid];
            s_hist[tid] = t;
        }
        __syncthreads();
        if (tid < 32) select_bin(s_hist, K, 0u, &s_prefix, &s_kr, lane);
        // re-zero per-warp hists for sweep B (disjoint from s_hist scan)
        #pragma unroll
        for (int j = lane; j < 256; j += 32) s_wh[wid * 256 + j] = 0;
        __syncthreads();
        const unsigned b0 = s_prefix;
        int kr = s_kr;

        // ---- Sweep B: second byte among elements with top byte == b0 ----
        #pragma unroll
        for (int it = 0; it < NIT2; it++) {
            const int i4 = tid + it * T2;
            const bool valid = (i4 < NQ);
            uint4 w = make_uint4(0, 0, 0, 0);
            if (valid) w = ((const uint4*)s_bits)[i4];
            #pragma unroll
            for (int c = 0; c < 4; c++) {
                unsigned u = (c == 0) ? w.x : (c == 1) ? w.y : (c == 2) ? w.z : w.w;
                bool ok = valid && ((u >> 24) == b0);
                unsigned bkt = ok ? ((u >> 16) & 255u) : 0x100u;
                unsigned m = __match_any_sync(0xFFFFFFFFu, bkt);
                if (ok && lane == (__ffs(m) - 1))
                    s_wh[wid * 256 + bkt] += __popc(m);
            }
        }
        __syncthreads();
        if (tid < 256) {
            int t = 0;
            #pragma unroll
            for (int w = 0; w < NW2; w++) t += s_wh[w * 256 + tid];
            s_hist[tid] = t;
        }
        __syncthreads();
        if (tid < 32) select_bin(s_hist, kr, b0, &s_prefix, &s_kr, lane);
        __syncthreads();
        const unsigned prefix16 = s_prefix;
        kr = s_kr;

        // ---- Sweep C: sum above prefix16; third-byte count+sum for the tie bin ----
        float sg = 0.f;
        #pragma unroll
        for (int it = 0; it < NIT2; it++) {
            const int i4 = tid + it * T2;
            if (i4 < NQ) {
                uint4 w = ((const uint4*)s_bits)[i4];
                #pragma unroll
                for (int c = 0; c < 4; c++) {
                    unsigned u = (c == 0) ? w.x : (c == 1) ? w.y : (c == 2) ? w.z : w.w;
                    unsigned hi = u >> 16;
                    if (hi > prefix16) {
                        sg += __uint_as_float(u);
                    } else if (hi == prefix16) {
                        unsigned bkt = (u >> 8) & 255u;
                        atomicAdd(&s_c2[bkt], 1);
                        atomicAdd(&s_fsum[bkt], __uint_as_float(u));
                    }
                }
            }
        }
        sg = warp_sum(sg);
        if (lane == 0) atomicAdd(&s_sumgt, sg);
        __syncthreads();

        if (tid < 32) select_bin(s_c2, kr, prefix16, &s_prefix, &s_kr, lane);
        __syncthreads();
        const int b2  = (int)(s_prefix & 255u);
        const int kr2 = s_kr;

        // sum of full sub-bins strictly above b2
        float v = (tid < 256 && tid > b2) ? s_fsum[tid] : 0.f;
        v = warp_sum(v);
        if (lane == 0 && v != 0.f) atomicAdd(&s_sumabove, v);
        __syncthreads();

        const int cb2 = s_c2[b2];
        const float avg = s_fsum[b2] / (float)(cb2 > 0 ? cb2 : 1);
        sum_top = s_sumgt + s_sumabove + (float)kr2 * avg;
    }

    // ---- Publish row result; last block reduces, writes output, resets ----
    if (tid == 0) {
        g_row_lossl[b] = g_row_bcepos[b] + sum_top;
        __threadfence();
        int prev = atomicAdd(&g_done, 1);
        s_last = (prev == BATCH - 1);
    }
    __syncthreads();

    if (s_last) {
        float vlb = 0.f, vll = 0.f, vm = 0.f;
        if (tid < BATCH) {
            float pn  = (float)((volatile int*)g_row_posn)[tid];
            float lbv = ((volatile float*)g_row_lossb)[tid];
            float llv = ((volatile float*)g_row_lossl)[tid];
            float mask = (pn > 0.f) ? 1.f : 0.f;
            float wgt  = mask / fmaxf(pn, FLT_EPS_);
            vlb = lbv * wgt;
            vll = llv * wgt;
            vm  = wgt;
            // reset accumulators for next graph replay
            g_row_posn[tid]   = 0;
            g_row_lossb[tid]  = 0.f;
            g_row_bcepos[tid] = 0.f;
        }
        vlb = warp_sum(vlb);
        vll = warp_sum(vll);
        vm  = warp_sum(vm);
        if (lane == 0) {
            s_red[wid * 3 + 0] = vlb;
            s_red[wid * 3 + 1] = vll;
            s_red[wid * 3 + 2] = vm;
        }
        __syncthreads();
        if (tid == 0) {
            float slb = 0.f, sll = 0.f, sm = 0.f;
            #pragma unroll
            for (int w = 0; w < NW2; w++) {
                slb += s_red[w * 3 + 0];
                sll += s_red[w * 3 + 1];
                sm  += s_red[w * 3 + 2];
            }
            const float lb = slb / (float)BATCH;
            const float ll = sll / (float)BATCH;
            const float total = (lb + ll) * (sm / (float)BATCH);
            if (out_size >= 1) out[0] = total;
            if (out_size >= 2) out[1] = lb;
            if (out_size >= 3) out[2] = ll;
            g_done = 0;
        }
    }
}

extern "C" void kernel_launch(void* const* d_in, const int* in_sizes, int n_in,
                              void* d_out, int out_size) {
    const float* pbboxs  = (const float*)d_in[0];
    const float* plabels = (const float*)d_in[1];
    const float* gbboxs  = (const float*)d_in[2];
    const float* glabels = (const float*)d_in[3];
    const float* ancs    = (const float*)d_in[4];
    (void)in_sizes; (void)n_in;

    const size_t smem = (size_t)NANCH * sizeof(unsigned);
    cudaFuncSetAttribute(od_pass2,
                         cudaFuncAttributeMaxDynamicSharedMemorySize, (int)smem);

    dim3 grid1(CHUNKS, BATCH);
    od_pass1<<<grid1, T1>>>(pbboxs, plabels, gbboxs, glabels, ancs);
    od_pass2<<<BATCH, T2, smem>>>((float*)d_out, out_size);
}

// round 5
// speedup vs baseline: 2.1092x; 1.9133x over previous
#include <cuda_runtime.h>
#include <stdint.h>

#define BATCH 128
#define NANCH 16800
#define NQ (NANCH / 4)            // 4200 uint4/float4 per row
#define NEG_RATIO 3
#define SCALE_XY 10.0f
#define SCALE_WH 5.0f
#define T 1024
#define NW (T / 32)               // 32 warps
#define NIT ((NQ + T - 1) / T)    // 5
#define NBINS 34816               // float_bits >> 15, covers values < 512
#define CHB (NBINS / T)           // 34 bins per thread
#define FLT_EPS_ 1.1920929e-07f

// Cross-block scratch (allocation-free rule: __device__ globals)
__device__ float g_row_lossb[BATCH];
__device__ float g_row_lossl[BATCH];
__device__ int   g_row_posn[BATCH];
__device__ int   g_done = 0;

extern __shared__ unsigned s_dyn[];  // [NBINS] hist | [NANCH] bits

__device__ __forceinline__ float warp_sum(float v) {
    #pragma unroll
    for (int o = 16; o > 0; o >>= 1) v += __shfl_down_sync(0xFFFFFFFFu, v, o);
    return v;
}
__device__ __forceinline__ int warp_sum_i(int v) {
    #pragma unroll
    for (int o = 16; o > 0; o >>= 1) v += __shfl_down_sync(0xFFFFFFFFu, v, o);
    return v;
}
// suffix-inclusive scan within warp: result(lane) = sum over lanes >= lane
__device__ __forceinline__ int warp_suffix_incl(int v, int lane) {
    #pragma unroll
    for (int o = 1; o < 32; o <<= 1) {
        int u = __shfl_down_sync(0xFFFFFFFFu, v, o);
        if (lane + o < 32) v += u;
    }
    return v;
}

__global__ __launch_bounds__(T, 1)
void od_fused(const float* __restrict__ pbboxs,
              const float* __restrict__ plabels,
              const float* __restrict__ gbboxs,
              const float* __restrict__ glabels,
              const float* __restrict__ ancs,
              float* __restrict__ out, int out_size) {
    const int b    = blockIdx.x;
    const int tid  = threadIdx.x;
    const int lane = tid & 31;
    const int wid  = tid >> 5;

    int*      s_hist = (int*)s_dyn;
    unsigned* s_bits = s_dyn + NBINS;

    __shared__ float s_sl1, s_bce, s_above, s_tsum;
    __shared__ int   s_cnt, s_tbin, s_kr, s_last;
    __shared__ int   s_wtot[NW], s_wsuf[NW];
    __shared__ float s_red[NW * 3];

    // ---- init ----
    for (int j = tid; j < NBINS; j += T) s_hist[j] = 0;
    if (tid == 0) { s_sl1 = 0.f; s_bce = 0.f; s_above = 0.f; s_tsum = 0.f; s_cnt = 0; }
    __syncthreads();

    const float4* pl4 = (const float4*)(plabels + (size_t)b * NANCH);
    const float4* gl4 = (const float4*)(glabels + (size_t)b * NANCH);
    const float4* pb  = (const float4*)pbboxs + (size_t)b * NANCH;
    const float4* gb  = (const float4*)gbboxs + (size_t)b * NANCH;
    const float4* an  = (const float4*)ancs;

    // ---- Main pass: BCE + positive SmoothL1 + histogram + smem store ----
    float acc_sl1 = 0.f, acc_bce = 0.f;
    int cnt = 0;
    #pragma unroll
    for (int it = 0; it < NIT; it++) {
        const int i4 = tid + it * T;
        if (i4 < NQ) {
            float4 xv = pl4[i4];
            float4 yv = gl4[i4];
            uint4 w;
            #pragma unroll
            for (int c = 0; c < 4; c++) {
                float x = (c == 0) ? xv.x : (c == 1) ? xv.y : (c == 2) ? xv.z : xv.w;
                float y = (c == 0) ? yv.x : (c == 1) ? yv.y : (c == 2) ? yv.z : yv.w;
                float bce = fmaxf(x, 0.f) - x * y + __logf(1.f + __expf(-fabsf(x)));
                unsigned bits;
                if (y > 0.f) {
                    const int i = 4 * i4 + c;
                    float4 p = pb[i];
                    float4 g = gb[i];
                    float4 a = an[i];
                    float inv_az = 1.f / a.z;
                    float inv_aw = 1.f / a.w;
                    float d0 = p.x - SCALE_XY * (g.x - a.x) * inv_az;
                    float d1 = p.y - SCALE_XY * (g.y - a.y) * inv_aw;
                    float d2 = p.z - SCALE_WH * __logf(g.z * inv_az);
                    float d3 = p.w - SCALE_WH * __logf(g.w * inv_aw);
                    float sl1 = 0.f, ad;
                    ad = fabsf(d0); sl1 += (ad < 1.f) ? 0.5f * d0 * d0 : ad - 0.5f;
                    ad = fabsf(d1); sl1 += (ad < 1.f) ? 0.5f * d1 * d1 : ad - 0.5f;
                    ad = fabsf(d2); sl1 += (ad < 1.f) ? 0.5f * d2 * d2 : ad - 0.5f;
                    ad = fabsf(d3); sl1 += (ad < 1.f) ? 0.5f * d3 * d3 : ad - 0.5f;
                    acc_sl1 += sl1;
                    acc_bce += bce;
                    cnt++;
                    bits = 0u;
                } else {
                    bits = __float_as_uint(bce);  // bce >= 0: bit order == value order
                }
                unsigned bin = bits >> 15;
                if (bin > NBINS - 1) bin = NBINS - 1;
                atomicAdd(&s_hist[bin], 1);
                if (c == 0) w.x = bits; else if (c == 1) w.y = bits;
                else if (c == 2) w.z = bits; else w.w = bits;
            }
            ((uint4*)s_bits)[i4] = w;
        }
    }
    {
        float w1 = warp_sum(acc_sl1);
        float w2 = warp_sum(acc_bce);
        int   w3 = warp_sum_i(cnt);
        if (lane == 0) {
            if (w1 != 0.f) atomicAdd(&s_sl1, w1);
            if (w2 != 0.f) atomicAdd(&s_bce, w2);
            if (w3 != 0)   atomicAdd(&s_cnt, w3);
        }
    }
    __syncthreads();

    const int pos_num = s_cnt;
    int K = NEG_RATIO * pos_num;
    if (K > NANCH) K = NANCH;

    float sum_top = 0.f;
    if (K > 0) {
        // ---- Cooperative suffix-scan over NBINS to find threshold bin ----
        const int base = tid * CHB;
        int tot = 0;
        #pragma unroll
        for (int j = 0; j < CHB; j++) tot += s_hist[base + j];

        int incl = warp_suffix_incl(tot, lane);
        if (lane == 0) s_wtot[wid] = incl;  // warp total (suffix at lane 0)
        __syncthreads();
        if (tid < 32) {
            int wv = s_wtot[lane];
            int wincl = warp_suffix_incl(wv, lane);
            s_wsuf[lane] = wincl - wv;      // sum over warps strictly above
        }
        __syncthreads();
        const int excl = (incl - tot) + s_wsuf[wid];  // count in bins above my chunk

        if (excl < K && excl + tot >= K) {
            int cum = excl;
            #pragma unroll
            for (int j = CHB - 1; j >= 0; j--) {
                int h = s_hist[base + j];
                cum += h;
                if (cum >= K) {
                    s_tbin = base + j;
                    s_kr   = K - (cum - h);
                    break;
                }
            }
        }
        __syncthreads();
        const unsigned tbin = (unsigned)s_tbin;
        const int kr = s_kr;

        // ---- Final sweep: exact sum above threshold bin + exact tie-bin sum ----
        float sg = 0.f;
        float tie = 0.f;
        #pragma unroll
        for (int it = 0; it < NIT; it++) {
            const int i4 = tid + it * T;
            if (i4 < NQ) {
                uint4 w = ((const uint4*)s_bits)[i4];
                #pragma unroll
                for (int c = 0; c < 4; c++) {
                    unsigned u = (c == 0) ? w.x : (c == 1) ? w.y : (c == 2) ? w.z : w.w;
                    unsigned bin = u >> 15;
                    if (bin > NBINS - 1) bin = NBINS - 1;
                    if (bin > tbin)       sg  += __uint_as_float(u);
                    else if (bin == tbin) tie += __uint_as_float(u);
                }
            }
        }
        sg  = warp_sum(sg);
        tie = warp_sum(tie);
        if (lane == 0) {
            if (sg  != 0.f) atomicAdd(&s_above, sg);
            if (tie != 0.f) atomicAdd(&s_tsum, tie);
        }
        __syncthreads();

        const int tcnt = s_hist[tbin];
        const float avg = s_tsum / (float)(tcnt > 0 ? tcnt : 1);
        sum_top = s_above + (float)kr * avg;
    }

    // ---- Publish row; last block does the final reduction ----
    if (tid == 0) {
        g_row_posn[b]  = pos_num;
        g_row_lossb[b] = s_sl1;
        g_row_lossl[b] = s_bce + sum_top;
        __threadfence();
        int prev = atomicAdd(&g_done, 1);
        s_last = (prev == BATCH - 1);
    }
    __syncthreads();

    if (s_last) {
        float vlb = 0.f, vll = 0.f, vm = 0.f;
        if (tid < BATCH) {
            float pn  = (float)((volatile int*)g_row_posn)[tid];
            float lbv = ((volatile float*)g_row_lossb)[tid];
            float llv = ((volatile float*)g_row_lossl)[tid];
            float mask = (pn > 0.f) ? 1.f : 0.f;
            float wgt  = mask / fmaxf(pn, FLT_EPS_);
            vlb = lbv * wgt;
            vll = llv * wgt;
            vm  = wgt;
        }
        vlb = warp_sum(vlb);
        vll = warp_sum(vll);
        vm  = warp_sum(vm);
        if (lane == 0) {
            s_red[wid * 3 + 0] = vlb;
            s_red[wid * 3 + 1] = vll;
            s_red[wid * 3 + 2] = vm;
        }
        __syncthreads();
        if (tid == 0) {
            float slb = 0.f, sll = 0.f, sm = 0.f;
            #pragma unroll
            for (int w = 0; w < NW; w++) {
                slb += s_red[w * 3 + 0];
                sll += s_red[w * 3 + 1];
                sm  += s_red[w * 3 + 2];
            }
            const float lb = slb / (float)BATCH;
            const float ll = sll / (float)BATCH;
            const float total = (lb + ll) * (sm / (float)BATCH);
            if (out_size >= 1) out[0] = total;
            if (out_size >= 2) out[1] = lb;
            if (out_size >= 3) out[2] = ll;
            g_done = 0;  // reset for next graph replay
        }
    }
}

extern "C" void kernel_launch(void* const* d_in, const int* in_sizes, int n_in,
                              void* d_out, int out_size) {
    const float* pbboxs  = (const float*)d_in[0];
    const float* plabels = (const float*)d_in[1];
    const float* gbboxs  = (const float*)d_in[2];
    const float* glabels = (const float*)d_in[3];
    const float* ancs    = (const float*)d_in[4];
    (void)in_sizes; (void)n_in;

    const size_t smem = ((size_t)NBINS + NANCH) * sizeof(unsigned);  // ~201.6 KB
    cudaFuncSetAttribute(od_fused,
                         cudaFuncAttributeMaxDynamicSharedMemorySize, (int)smem);

    od_fused<<<BATCH, T, smem>>>(pbboxs, plabels, gbboxs, glabels, ancs,
                                 (float*)d_out, out_size);
}